// round 1
// baseline (speedup 1.0000x reference)
#include <cuda_runtime.h>

#define BATCH 8
#define SEQ   2500
#define DIM   128
#define NCLS  8921
#define CT    128           // class tile
#define LT    128           // seq chunk
#define NCHUNK ((SEQ + LT - 1) / LT)   // 20
#define THREADS 256
#define STRIDE 129          // smem row stride in floats (conflict-avoiding)

// smem: Us[CT][STRIDE] | xL[LT][STRIDE] | P[CT][STRIDE]
#define SMEM_FLOATS (3 * CT * STRIDE)
#define SMEM_BYTES  (SMEM_FLOATS * 4)

__global__ __launch_bounds__(THREADS, 1)
void lwa_kernel(const float* __restrict__ x,
                const float* __restrict__ U,
                float* __restrict__ out)
{
    extern __shared__ float smem[];
    float* Us = smem;                    // [CT][STRIDE]
    float* xL = smem + CT * STRIDE;      // [LT][STRIDE]
    float* P  = xL   + LT * STRIDE;      // [CT][STRIDE]

    const int b  = blockIdx.y;
    const int c0 = blockIdx.x * CT;

    const int tid = threadIdx.x;
    const int tx  = tid & 15;            // 0..15  -> owns d/l columns {tx + 16*j}
    const int ty  = tid >> 4;            // 0..15  -> owns c rows {ty*8 + i}

    // ---- load U tile into smem (once) ----
    for (int idx = tid; idx < CT * DIM; idx += THREADS) {
        int r   = idx >> 7;      // /128
        int col = idx & 127;
        int c   = c0 + r;
        Us[r * STRIDE + col] = (c < NCLS) ? U[c * DIM + col] : 0.0f;
    }

    float O[8][8];
    float row_max[8], row_sum[8];
    #pragma unroll
    for (int i = 0; i < 8; i++) {
        row_max[i] = -1e30f;
        row_sum[i] = 0.0f;
        #pragma unroll
        for (int j = 0; j < 8; j++) O[i][j] = 0.0f;
    }

    const float* xb = x + (size_t)b * SEQ * DIM;

    for (int ch = 0; ch < NCHUNK; ++ch) {
        const int l0 = ch * LT;
        const int lvalid = (SEQ - l0 < LT) ? (SEQ - l0) : LT;

        // protect previous iteration's reads of xL / P
        __syncthreads();

        // ---- load x chunk: xL[l][d], float4 global reads, float4-ish stores ----
        for (int idx = tid; idx < LT * (DIM / 4); idx += THREADS) {
            int r  = idx >> 5;           // /32 float4 per row
            int c4 = idx & 31;
            float4 v = make_float4(0.f, 0.f, 0.f, 0.f);
            if (r < lvalid)
                v = ((const float4*)(xb + (size_t)(l0 + r) * DIM))[c4];
            float* dst = xL + r * STRIDE + c4 * 4;
            dst[0] = v.x; dst[1] = v.y; dst[2] = v.z; dst[3] = v.w;
        }
        __syncthreads();

        // ---- S = Us @ xL^T  (S[i][j]: row c0+ty*8+i, col l0+tx+16*j) ----
        float S[8][8];
        #pragma unroll
        for (int i = 0; i < 8; i++)
            #pragma unroll
            for (int j = 0; j < 8; j++) S[i][j] = 0.0f;

        #pragma unroll 2
        for (int k = 0; k < DIM; k++) {
            float a[8], bb[8];
            #pragma unroll
            for (int i = 0; i < 8; i++) a[i]  = Us[(ty * 8 + i) * STRIDE + k];
            #pragma unroll
            for (int j = 0; j < 8; j++) bb[j] = xL[(tx + 16 * j) * STRIDE + k];
            #pragma unroll
            for (int i = 0; i < 8; i++)
                #pragma unroll
                for (int j = 0; j < 8; j++)
                    S[i][j] = fmaf(a[i], bb[j], S[i][j]);
        }

        // ---- mask invalid seq positions ----
        #pragma unroll
        for (int j = 0; j < 8; j++) {
            int l = tx + 16 * j;
            if (l >= lvalid) {
                #pragma unroll
                for (int i = 0; i < 8; i++) S[i][j] = -1e30f;
            }
        }

        // ---- online softmax (row stats reduced across the 16 tx lanes) ----
        #pragma unroll
        for (int i = 0; i < 8; i++) {
            float mloc = S[i][0];
            #pragma unroll
            for (int j = 1; j < 8; j++) mloc = fmaxf(mloc, S[i][j]);
            #pragma unroll
            for (int m = 1; m < 16; m <<= 1)
                mloc = fmaxf(mloc, __shfl_xor_sync(0xffffffffu, mloc, m));

            float mnew = fmaxf(row_max[i], mloc);
            float corr = __expf(row_max[i] - mnew);
            row_max[i] = mnew;

            float s = 0.0f;
            #pragma unroll
            for (int j = 0; j < 8; j++) {
                float p = __expf(S[i][j] - mnew);
                S[i][j] = p;                  // S now holds P fragment
                s += p;
            }
            #pragma unroll
            for (int m = 1; m < 16; m <<= 1)
                s += __shfl_xor_sync(0xffffffffu, s, m);

            row_sum[i] = row_sum[i] * corr + s;
            #pragma unroll
            for (int j = 0; j < 8; j++) O[i][j] *= corr;
        }

        // ---- write P to smem ----
        #pragma unroll
        for (int i = 0; i < 8; i++)
            #pragma unroll
            for (int j = 0; j < 8; j++)
                P[(ty * 8 + i) * STRIDE + tx + 16 * j] = S[i][j];
        __syncthreads();

        // ---- O += P @ xL  (O[i][j]: row c0+ty*8+i, col d = tx+16*j) ----
        #pragma unroll 2
        for (int l = 0; l < lvalid; l++) {
            float pa[8], bb[8];
            #pragma unroll
            for (int i = 0; i < 8; i++) pa[i] = P[(ty * 8 + i) * STRIDE + l];
            #pragma unroll
            for (int j = 0; j < 8; j++) bb[j] = xL[l * STRIDE + tx + 16 * j];
            #pragma unroll
            for (int i = 0; i < 8; i++)
                #pragma unroll
                for (int j = 0; j < 8; j++)
                    O[i][j] = fmaf(pa[i], bb[j], O[i][j]);
        }
    }

    // ---- normalize + store ----
    #pragma unroll
    for (int i = 0; i < 8; i++) {
        int c = c0 + ty * 8 + i;
        if (c >= NCLS) continue;
        float inv = 1.0f / row_sum[i];
        float* orow = out + ((size_t)b * NCLS + c) * DIM;
        #pragma unroll
        for (int j = 0; j < 8; j++)
            orow[tx + 16 * j] = O[i][j] * inv;
    }
}

extern "C" void kernel_launch(void* const* d_in, const int* in_sizes, int n_in,
                              void* d_out, int out_size)
{
    const float* x = (const float*)d_in[0];   // [8, 2500, 128]
    const float* U = (const float*)d_in[1];   // [8921, 128]
    float* out = (float*)d_out;               // [8, 8921, 128]

    cudaFuncSetAttribute(lwa_kernel,
                         cudaFuncAttributeMaxDynamicSharedMemorySize,
                         SMEM_BYTES);

    dim3 grid((NCLS + CT - 1) / CT, BATCH);   // (70, 8)
    lwa_kernel<<<grid, THREADS, SMEM_BYTES>>>(x, U, out);
}

// round 2
// speedup vs baseline: 1.1769x; 1.1769x over previous
#include <cuda_runtime.h>

#define BATCH 8
#define SEQ   2500
#define DIM   128
#define NCLS  8921
#define CT    128
#define LT    128
#define NCHUNK ((SEQ + LT - 1) / LT)   // 20
#define THREADS 256
#define STRIDE 129

#define SMEM_FLOATS (3 * CT * STRIDE)
#define SMEM_BYTES  (SMEM_FLOATS * 4)

typedef unsigned long long u64;

__device__ __forceinline__ u64 pack2(float lo, float hi) {
    u64 r; asm("mov.b64 %0, {%1, %2};" : "=l"(r) : "f"(lo), "f"(hi)); return r;
}
__device__ __forceinline__ u64 rep2(float v) {
    u64 r; asm("mov.b64 %0, {%1, %1};" : "=l"(r) : "f"(v)); return r;
}
__device__ __forceinline__ void unpack2(u64 v, float& lo, float& hi) {
    asm("mov.b64 {%0, %1}, %2;" : "=f"(lo), "=f"(hi) : "l"(v));
}
__device__ __forceinline__ void fma2(u64& d, u64 a, u64 b) {
    asm("fma.rn.f32x2 %0, %1, %2, %0;" : "+l"(d) : "l"(a), "l"(b));
}
__device__ __forceinline__ void mul2(u64& d, u64 a) {
    asm("mul.rn.f32x2 %0, %0, %1;" : "+l"(d) : "l"(a));
}

__global__ __launch_bounds__(THREADS, 1)
void lwa_kernel(const float* __restrict__ x,
                const float* __restrict__ U,
                float* __restrict__ out)
{
    extern __shared__ float smem[];
    float* Us = smem;                    // [CT][STRIDE]
    float* xL = smem + CT * STRIDE;      // [LT][STRIDE]
    float* P  = xL   + LT * STRIDE;      // [CT][STRIDE]

    const int b  = blockIdx.y;
    const int c0 = blockIdx.x * CT;

    const int tid = threadIdx.x;
    const int tx  = tid & 15;            // owns columns {tx + 16*j}, j=0..7
    const int ty  = tid >> 4;            // owns rows {ty*8 + i}, i=0..7

    for (int idx = tid; idx < CT * DIM; idx += THREADS) {
        int r   = idx >> 7;
        int col = idx & 127;
        int c   = c0 + r;
        Us[r * STRIDE + col] = (c < NCLS) ? U[c * DIM + col] : 0.0f;
    }

    // O accumulator packed: O2[i][jp] holds (O[i][2jp], O[i][2jp+1])
    u64 O2[8][4];
    float row_max[8], row_sum[8];
    #pragma unroll
    for (int i = 0; i < 8; i++) {
        row_max[i] = -1e30f;
        row_sum[i] = 0.0f;
        #pragma unroll
        for (int jp = 0; jp < 4; jp++) O2[i][jp] = 0ull;
    }

    const float* xb = x + (size_t)b * SEQ * DIM;

    for (int ch = 0; ch < NCHUNK; ++ch) {
        const int l0 = ch * LT;
        const int lvalid = (SEQ - l0 < LT) ? (SEQ - l0) : LT;

        __syncthreads();

        // ---- load x chunk (float4) ----
        for (int idx = tid; idx < LT * (DIM / 4); idx += THREADS) {
            int r  = idx >> 5;
            int c4 = idx & 31;
            float4 v = make_float4(0.f, 0.f, 0.f, 0.f);
            if (r < lvalid)
                v = ((const float4*)(xb + (size_t)(l0 + r) * DIM))[c4];
            float* dst = xL + r * STRIDE + c4 * 4;
            dst[0] = v.x; dst[1] = v.y; dst[2] = v.z; dst[3] = v.w;
        }
        __syncthreads();

        // ---- S = Us @ xL^T, packed: S2[i][jp] = (S[i][2jp], S[i][2jp+1]) ----
        u64 S2[8][4];
        #pragma unroll
        for (int i = 0; i < 8; i++)
            #pragma unroll
            for (int jp = 0; jp < 4; jp++) S2[i][jp] = 0ull;

        #pragma unroll 2
        for (int k = 0; k < DIM; k++) {
            u64 arep[8], b2[4];
            #pragma unroll
            for (int i = 0; i < 8; i++)
                arep[i] = rep2(Us[(ty * 8 + i) * STRIDE + k]);
            #pragma unroll
            for (int jp = 0; jp < 4; jp++)
                b2[jp] = pack2(xL[(tx + 32 * jp) * STRIDE + k],
                               xL[(tx + 16 + 32 * jp) * STRIDE + k]);
            #pragma unroll
            for (int i = 0; i < 8; i++)
                #pragma unroll
                for (int jp = 0; jp < 4; jp++)
                    fma2(S2[i][jp], arep[i], b2[jp]);
        }

        // ---- unpack, mask, online softmax ----
        float S[8][8];
        #pragma unroll
        for (int i = 0; i < 8; i++)
            #pragma unroll
            for (int jp = 0; jp < 4; jp++)
                unpack2(S2[i][jp], S[i][2 * jp], S[i][2 * jp + 1]);

        #pragma unroll
        for (int j = 0; j < 8; j++) {
            int l = tx + 16 * j;
            if (l >= lvalid) {
                #pragma unroll
                for (int i = 0; i < 8; i++) S[i][j] = -1e30f;
            }
        }

        #pragma unroll
        for (int i = 0; i < 8; i++) {
            float mloc = S[i][0];
            #pragma unroll
            for (int j = 1; j < 8; j++) mloc = fmaxf(mloc, S[i][j]);
            #pragma unroll
            for (int m = 1; m < 16; m <<= 1)
                mloc = fmaxf(mloc, __shfl_xor_sync(0xffffffffu, mloc, m));

            float mnew = fmaxf(row_max[i], mloc);
            float corr = __expf(row_max[i] - mnew);
            row_max[i] = mnew;

            float s = 0.0f;
            #pragma unroll
            for (int j = 0; j < 8; j++) {
                float p = __expf(S[i][j] - mnew);
                S[i][j] = p;
                s += p;
            }
            #pragma unroll
            for (int m = 1; m < 16; m <<= 1)
                s += __shfl_xor_sync(0xffffffffu, s, m);

            row_sum[i] = row_sum[i] * corr + s;

            u64 corr2 = rep2(corr);
            #pragma unroll
            for (int jp = 0; jp < 4; jp++) mul2(O2[i][jp], corr2);
        }

        // ---- write P ----
        #pragma unroll
        for (int i = 0; i < 8; i++)
            #pragma unroll
            for (int j = 0; j < 8; j++)
                P[(ty * 8 + i) * STRIDE + tx + 16 * j] = S[i][j];
        __syncthreads();

        // ---- O += P @ xL, packed over d pairs (d = tx+16*(2jp), tx+16*(2jp+1)) ----
        #pragma unroll 2
        for (int l = 0; l < lvalid; l++) {
            u64 parep[8], b2[4];
            #pragma unroll
            for (int i = 0; i < 8; i++)
                parep[i] = rep2(P[(ty * 8 + i) * STRIDE + l]);
            #pragma unroll
            for (int jp = 0; jp < 4; jp++)
                b2[jp] = pack2(xL[l * STRIDE + tx + 32 * jp],
                               xL[l * STRIDE + tx + 16 + 32 * jp]);
            #pragma unroll
            for (int i = 0; i < 8; i++)
                #pragma unroll
                for (int jp = 0; jp < 4; jp++)
                    fma2(O2[i][jp], parep[i], b2[jp]);
        }
    }

    // ---- normalize + store ----
    #pragma unroll
    for (int i = 0; i < 8; i++) {
        int c = c0 + ty * 8 + i;
        if (c >= NCLS) continue;
        float inv = 1.0f / row_sum[i];
        float* orow = out + ((size_t)b * NCLS + c) * DIM;
        #pragma unroll
        for (int jp = 0; jp < 4; jp++) {
            float lo, hi;
            unpack2(O2[i][jp], lo, hi);
            orow[tx + 32 * jp]      = lo * inv;
            orow[tx + 16 + 32 * jp] = hi * inv;
        }
    }
}

extern "C" void kernel_launch(void* const* d_in, const int* in_sizes, int n_in,
                              void* d_out, int out_size)
{
    const float* x = (const float*)d_in[0];
    const float* U = (const float*)d_in[1];
    float* out = (float*)d_out;

    cudaFuncSetAttribute(lwa_kernel,
                         cudaFuncAttributeMaxDynamicSharedMemorySize,
                         SMEM_BYTES);

    dim3 grid((NCLS + CT - 1) / CT, BATCH);
    lwa_kernel<<<grid, THREADS, SMEM_BYTES>>>(x, U, out);
}